// round 10
// baseline (speedup 1.0000x reference)
#include <cuda_runtime.h>
#include <cuda_fp16.h>
#include <cstdint>
#include <math.h>

#define NN      100000
#define NE      500000
#define LEAKY   0.001f
#define LN_EPS  1e-5f
#define DIST_MAX 20.0f
#define STEPU   0.5f
#define RSTP    (DIST_MAX / 62.f)
#define RCOE    (-0.5f / (RSTP * RSTP))

// ---------------- static device scratch ----------------
__device__ float g_P[(size_t)NN * 128];
__device__ float g_Q[(size_t)NN * 128];
__device__ float g_T[512];
__device__ uint2 g_WAh[4096];   // W0[0:128]   fp16 frag image (K=128)
__device__ uint2 g_WBh[4096];   // W0[128:256] fp16 frag image (K=128)
__device__ uint2 g_WDh[2048];   // W0[320:384] fp16 frag image (K=64)
__device__ uint2 g_W1h[4096];   // W1 fp16 frag image
__device__ uint2 g_W2h[4096];   // W2 fp16 frag image

// ---------------- helpers ----------------
__device__ __forceinline__ float lrelu(float v) { return v >= 0.f ? v : LEAKY * v; }
__device__ __forceinline__ uint32_t h2u(half2 h) { return *(uint32_t*)&h; }

__device__ __forceinline__ uint32_t smem_u32(const void* p) {
    uint32_t a;
    asm("{ .reg .u64 t; cvta.to.shared.u64 t, %1; cvt.u32.u64 %0, t; }" : "=r"(a) : "l"(p));
    return a;
}

// mma.sync m16n8k16 f16 inputs, f32 accumulate, C in-place
__device__ __forceinline__ void mma16(float c[4], uint32_t a0, uint32_t a1,
                                      uint32_t a2, uint32_t a3, uint2 b) {
    asm("mma.sync.aligned.m16n8k16.row.col.f32.f16.f16.f32 "
        "{%0,%1,%2,%3}, {%4,%5,%6,%7}, {%8,%9}, {%0,%1,%2,%3};"
        : "+f"(c[0]), "+f"(c[1]), "+f"(c[2]), "+f"(c[3])
        : "r"(a0), "r"(a1), "r"(a2), "r"(a3), "r"(b.x), "r"(b.y));
}

// A-fragments via ldmatrix.x4 from row-major fp16 staging (row pitch 272B).
// abase = staging base + (ln&15)*272 + (ln>>4)*16  (per-lane, fixed per tile)
__device__ __forceinline__ void run_layer_h(float c[16][4], uint32_t abase,
                                            const uint2* __restrict__ wf, int nkt, int ln) {
    #pragma unroll 4
    for (int kt = 0; kt < nkt; kt++) {
        uint32_t a0, a1, a2, a3;
        asm volatile("ldmatrix.sync.aligned.m8n8.x4.shared.b16 {%0,%1,%2,%3}, [%4];"
                     : "=r"(a0), "=r"(a1), "=r"(a2), "=r"(a3)
                     : "r"(abase + kt * 32));
        #pragma unroll
        for (int nt = 0; nt < 16; nt++)
            mma16(c[nt], a0, a1, a2, a3, wf[(kt * 16 + nt) * 32 + ln]);
    }
}

__device__ __forceinline__ float smear_raw(float d, int k) {
    if (k == 63) return (d >= DIST_MAX) ? 1.f : 0.f;
    float tt = d - (float)k * RSTP;
    return __expf(RCOE * tt * tt);
}

// ---------------- prep kernels ----------------
__global__ void bond_table_kernel(const float* __restrict__ be,
                                  const float* __restrict__ W0,
                                  const float* __restrict__ b0) {
    int t = threadIdx.x;            // 512 threads
    int bt = t >> 7, c = t & 127;
    float acc = b0[c];
    #pragma unroll 8
    for (int k = 0; k < 64; k++)
        acc += be[bt * 64 + k] * W0[(256 + k) * 128 + c];
    g_T[t] = acc;
}

// Pack W (K x 128 row-major) into m16n8k16 B-fragment order (fp16).
__device__ __forceinline__ void pack_seg(const float* __restrict__ W, uint2* __restrict__ dst, int f) {
    int ln = f & 31, ntk = f >> 5;
    int nt = ntk & 15, kt = ntk >> 4;
    int t = ln & 3, g = ln >> 2;
    int n = nt * 8 + g, k0 = kt * 16 + 2 * t;
    half2 lo = __floats2half2_rn(W[k0 * 128 + n],       W[(k0 + 1) * 128 + n]);
    half2 hi = __floats2half2_rn(W[(k0 + 8) * 128 + n], W[(k0 + 9) * 128 + n]);
    dst[f] = make_uint2(h2u(lo), h2u(hi));
}

__global__ void pack_all(const float* __restrict__ W0, const float* __restrict__ W1,
                         const float* __restrict__ W2) {
    int idx = blockIdx.x * 256 + threadIdx.x;
    if (idx < 4096)       pack_seg(W0,              g_WAh, idx);
    else if (idx < 8192)  pack_seg(W0 + 128 * 128,  g_WBh, idx - 4096);
    else if (idx < 10240) pack_seg(W0 + 320 * 128,  g_WDh, idx - 8192);
    else if (idx < 14336) pack_seg(W1,              g_W1h, idx - 10240);
    else if (idx < 18432) pack_seg(W2,              g_W2h, idx - 14336);
}

// ---------------- node precompute: P = ne@W0a, Q = ne@W0b (+ pos copy) ----------------
// smem bytes: WAh [0,32768) | WBh [32768,65536) | staging @65536: 8 warps x 4352B
#define PQ_SMEM 100352
__global__ void __launch_bounds__(256, 2)
pq_kernel(const float* __restrict__ ne, const float* __restrict__ pos, float* __restrict__ out) {
    extern __shared__ unsigned char sm8[];
    uint2* was = (uint2*)sm8;
    uint2* wbs = (uint2*)(sm8 + 32768);
    const int tid = threadIdx.x, ln = tid & 31, wid = tid >> 5;
    const int g = ln >> 2, t = ln & 3;

    // fused: initialize output with pos
    for (int i = blockIdx.x * 256 + tid; i < 3 * NN; i += gridDim.x * 256)
        out[i] = pos[i];

    {
        const uint2* A = g_WAh; const uint2* B = g_WBh;
        for (int i = tid; i < 4096; i += 256) { was[i] = A[i]; wbs[i] = B[i]; }
    }
    __syncthreads();

    const int R = blockIdx.x * 128 + wid * 16;
    half2* stgw = (half2*)(sm8 + 65536) + wid * 1088;
    const uint32_t abase = smem_u32(sm8) + 65536 + wid * 4352 + (ln & 15) * 272 + (ln >> 4) * 16;

    // stage ne rows (fp16): lane pair (rl, rl+16) covers row rl
    {
        int rl = ln & 15, h = ln >> 4;
        int row = R + rl;
        bool v = row < NN;
        const float4* src = (const float4*)(ne + (size_t)(v ? row : 0) * 128);
        #pragma unroll
        for (int q = 0; q < 8; q++) {
            float4 x1 = src[h * 16 + 2 * q];
            float4 x2 = src[h * 16 + 2 * q + 1];
            if (!v) { x1 = make_float4(0, 0, 0, 0); x2 = x1; }
            uint4 o;
            o.x = h2u(__floats2half2_rn(x1.x, x1.y));
            o.y = h2u(__floats2half2_rn(x1.z, x1.w));
            o.z = h2u(__floats2half2_rn(x2.x, x2.y));
            o.w = h2u(__floats2half2_rn(x2.z, x2.w));
            *(uint4*)&stgw[rl * 68 + h * 32 + q * 4] = o;
        }
    }
    __syncwarp();

    float c[16][4];
    const bool vlo = (R + g) < NN, vhi = (R + g + 8) < NN;

    #pragma unroll
    for (int nt = 0; nt < 16; nt++) { c[nt][0] = c[nt][1] = c[nt][2] = c[nt][3] = 0.f; }
    run_layer_h(c, abase, was, 8, ln);
    #pragma unroll
    for (int nt = 0; nt < 16; nt++) {
        int cp = nt * 4 + t;
        if (vlo) ((float2*)(g_P + (size_t)(R + g) * 128))[cp]     = make_float2(c[nt][0], c[nt][1]);
        if (vhi) ((float2*)(g_P + (size_t)(R + g + 8) * 128))[cp] = make_float2(c[nt][2], c[nt][3]);
    }

    #pragma unroll
    for (int nt = 0; nt < 16; nt++) { c[nt][0] = c[nt][1] = c[nt][2] = c[nt][3] = 0.f; }
    run_layer_h(c, abase, wbs, 8, ln);
    #pragma unroll
    for (int nt = 0; nt < 16; nt++) {
        int cp = nt * 4 + t;
        if (vlo) ((float2*)(g_Q + (size_t)(R + g) * 128))[cp]     = make_float2(c[nt][0], c[nt][1]);
        if (vhi) ((float2*)(g_Q + (size_t)(R + g + 8) * 128))[cp] = make_float2(c[nt][2], c[nt][3]);
    }
}

// ---------------- fused edge kernel (persistent, 640 thr / 20 warps) ----------------
// smem bytes: w0d [0,16384) | w1 [16384,49152) | w2 [49152,81920)
//   | T [81920,83968) | b1,l1w,l1b,b2,l2w,l2b [83968,87040) | Wo [87040,88064)
//   | staging @88064: 20 warps x 4352B -> total 175104
#define EG_SMEM 175104
#define NT_EDGE ((NE + 319) / 320)
__global__ void __launch_bounds__(640, 1)
edge_kernel(const float* __restrict__ x, const int* __restrict__ bidx, const int* __restrict__ btyp,
            const float* __restrict__ b1, const float* __restrict__ l1w, const float* __restrict__ l1b,
            const float* __restrict__ b2, const float* __restrict__ l2w, const float* __restrict__ l2b,
            const float* __restrict__ Wo, const float* __restrict__ bo, float* __restrict__ out) {
    extern __shared__ unsigned char sm8[];
    uint2* w0s = (uint2*)sm8;
    uint2* w1s = (uint2*)(sm8 + 16384);
    uint2* w2s = (uint2*)(sm8 + 49152);
    float* sT  = (float*)(sm8 + 81920);
    float* sB  = (float*)(sm8 + 83968);
    float* sWo = (float*)(sm8 + 87040);

    const int tid = threadIdx.x, ln = tid & 31, wid = tid >> 5;
    const int g = ln >> 2, t = ln & 3;
    const int rl = ln & 15, h = ln >> 4;

    {
        const uint2* A = g_WDh; const uint2* B = g_W1h; const uint2* C = g_W2h;
        for (int i = tid; i < 2048; i += 640) w0s[i] = A[i];
        for (int i = tid; i < 4096; i += 640) { w1s[i] = B[i]; w2s[i] = C[i]; }
    }
    if (tid < 512) sT[tid] = g_T[tid];
    if (tid < 128) {
        sB[tid] = b1[tid]; sB[128 + tid] = l1w[tid]; sB[256 + tid] = l1b[tid];
        sB[384 + tid] = b2[tid]; sB[512 + tid] = l2w[tid]; sB[640 + tid] = l2b[tid];
    }
    for (int i = tid; i < 256; i += 640) sWo[i] = Wo[i];
    __syncthreads();

    half2* stgw = (half2*)(sm8 + 88064) + wid * 1088;
    const uint32_t abase = smem_u32(sm8) + 88064 + wid * 4352 + rl * 272 + h * 16;
    const float bo0 = bo[0], bo1 = bo[1];
    const float2* P2 = (const float2*)g_P;
    const float2* Q2 = (const float2*)g_Q;
    const float2* T2 = (const float2*)sT;
    const float2* b1v = (const float2*)sB,         *w1v = (const float2*)(sB + 128), *l1v = (const float2*)(sB + 256);
    const float2* b2v = (const float2*)(sB + 384), *w2v = (const float2*)(sB + 512), *l2v = (const float2*)(sB + 640);
    const float2* wov = (const float2*)sWo;

    // prefetch state for this thread's edge row
    int pfi = 0, pfj = 0, pfbt = 0, pfv = 0;
    float pxi0 = 0, pxi1 = 0, pxi2 = 0, pxj0 = 0, pxj1 = 0, pxj2 = 0;
    {
        int ee = blockIdx.x * 320 + wid * 16 + rl;
        pfv = ee < NE;
        if (pfv) { pfi = bidx[2 * ee]; pfj = bidx[2 * ee + 1]; pfbt = btyp[ee]; }
        pxi0 = x[3 * pfi]; pxi1 = x[3 * pfi + 1]; pxi2 = x[3 * pfi + 2];
        pxj0 = x[3 * pfj]; pxj1 = x[3 * pfj + 1]; pxj2 = x[3 * pfj + 2];
    }

    for (int tile = blockIdx.x; tile < NT_EDGE; tile += gridDim.x) {
        const int ci = pfi, cj = pfj, cbt = pfbt, cval = pfv;
        const float dx = pxi0 - pxj0, dy = pxi1 - pxj1, dz = pxi2 - pxj2;
        const float dist = sqrtf(dx * dx + dy * dy + dz * dz);

        // ---- smear: raw RBF staged (fp16), partial sum; normalization deferred ----
        __syncwarp();   // prior tile's ldmatrix reads done before overwrite
        float part = 0.f;
        {
            int bk = h * 32;
            #pragma unroll
            for (int q = 0; q < 16; q++) {
                float v0 = smear_raw(dist, bk + 2 * q);
                float v1 = smear_raw(dist, bk + 2 * q + 1);
                part += v0 + v1;
                stgw[rl * 68 + h * 16 + q] = __floats2half2_rn(v0, v1);
            }
        }
        const float ssum = part + __shfl_xor_sync(~0u, part, 16);

        // issue next tile's loads (hide gather latency behind this tile's math)
        {
            int tl2 = tile + gridDim.x;
            if (tl2 < NT_EDGE) {
                int ee = tl2 * 320 + wid * 16 + rl;
                pfv = ee < NE;
                pfi = 0; pfj = 0; pfbt = 0;
                if (pfv) { pfi = bidx[2 * ee]; pfj = bidx[2 * ee + 1]; pfbt = btyp[ee]; }
                pxi0 = x[3 * pfi]; pxi1 = x[3 * pfi + 1]; pxi2 = x[3 * pfi + 2];
                pxj0 = x[3 * pfj]; pxj1 = x[3 * pfj + 1]; pxj2 = x[3 * pfj + 2];
            } else pfv = 0;
        }

        // broadcast gather scalars for fragment rows g, g+8
        const int   i_lo = __shfl_sync(~0u, ci, g),    i_hi = __shfl_sync(~0u, ci, g + 8);
        const int   j_lo = __shfl_sync(~0u, cj, g),    j_hi = __shfl_sync(~0u, cj, g + 8);
        const int   bt_lo = __shfl_sync(~0u, cbt, g),  bt_hi = __shfl_sync(~0u, cbt, g + 8);
        const float s_lo = __shfl_sync(~0u, ssum, g),  s_hi = __shfl_sync(~0u, ssum, g + 8);
        __syncwarp();

        // ---- C init = (P[i]+Q[j]+T[bt]) * s  (so raw-smear GEMM + this = s*(normalized result)) ----
        float c[16][4];
        #pragma unroll
        for (int nt = 0; nt < 16; nt++) {
            int cp = nt * 4 + t;
            float2 p = P2[(size_t)i_lo * 64 + cp], q = Q2[(size_t)j_lo * 64 + cp], tt = T2[bt_lo * 64 + cp];
            c[nt][0] = (p.x + q.x + tt.x) * s_lo; c[nt][1] = (p.y + q.y + tt.y) * s_lo;
            p = P2[(size_t)i_hi * 64 + cp]; q = Q2[(size_t)j_hi * 64 + cp]; tt = T2[bt_hi * 64 + cp];
            c[nt][2] = (p.x + q.x + tt.x) * s_hi; c[nt][3] = (p.y + q.y + tt.y) * s_hi;
        }

        // ---- L0: C += smear_raw @ W0d (K=64) ----
        run_layer_h(c, abase, w0s, 4, ln);

        // lrelu(C / s) -> fp16 stage
        const float rv_lo = 1.f / s_lo, rv_hi = 1.f / s_hi;
        __syncwarp();
        #pragma unroll
        for (int nt = 0; nt < 16; nt++) {
            stgw[g * 68 + nt * 4 + t]       = __floats2half2_rn(lrelu(c[nt][0] * rv_lo), lrelu(c[nt][1] * rv_lo));
            stgw[(g + 8) * 68 + nt * 4 + t] = __floats2half2_rn(lrelu(c[nt][2] * rv_hi), lrelu(c[nt][3] * rv_hi));
        }
        __syncwarp();

        // ---- L1 ----
        #pragma unroll
        for (int nt = 0; nt < 16; nt++) { c[nt][0] = c[nt][1] = c[nt][2] = c[nt][3] = 0.f; }
        run_layer_h(c, abase, w1s, 8, ln);
        {
            float slo = 0, sqlo = 0, shi = 0, sqhi = 0;
            #pragma unroll
            for (int nt = 0; nt < 16; nt++) {
                float2 bb = b1v[nt * 4 + t];
                c[nt][0] += bb.x; c[nt][1] += bb.y; c[nt][2] += bb.x; c[nt][3] += bb.y;
                slo += c[nt][0] + c[nt][1]; sqlo += c[nt][0] * c[nt][0] + c[nt][1] * c[nt][1];
                shi += c[nt][2] + c[nt][3]; sqhi += c[nt][2] * c[nt][2] + c[nt][3] * c[nt][3];
            }
            #pragma unroll
            for (int o = 1; o <= 2; o <<= 1) {
                slo += __shfl_xor_sync(~0u, slo, o); sqlo += __shfl_xor_sync(~0u, sqlo, o);
                shi += __shfl_xor_sync(~0u, shi, o); sqhi += __shfl_xor_sync(~0u, sqhi, o);
            }
            float mlo = slo * (1.f / 128.f), mhi = shi * (1.f / 128.f);
            float rlo = rsqrtf(sqlo * (1.f / 128.f) - mlo * mlo + LN_EPS);
            float rhi = rsqrtf(sqhi * (1.f / 128.f) - mhi * mhi + LN_EPS);
            __syncwarp();
            #pragma unroll
            for (int nt = 0; nt < 16; nt++) {
                float2 ww = w1v[nt * 4 + t], lb = l1v[nt * 4 + t];
                stgw[g * 68 + nt * 4 + t] = __floats2half2_rn(
                    lrelu((c[nt][0] - mlo) * rlo * ww.x + lb.x),
                    lrelu((c[nt][1] - mlo) * rlo * ww.y + lb.y));
                stgw[(g + 8) * 68 + nt * 4 + t] = __floats2half2_rn(
                    lrelu((c[nt][2] - mhi) * rhi * ww.x + lb.x),
                    lrelu((c[nt][3] - mhi) * rhi * ww.y + lb.y));
            }
            __syncwarp();
        }

        // ---- L2 ----
        #pragma unroll
        for (int nt = 0; nt < 16; nt++) { c[nt][0] = c[nt][1] = c[nt][2] = c[nt][3] = 0.f; }
        run_layer_h(c, abase, w2s, 8, ln);

        float f0lo = 0, f1lo = 0, f0hi = 0, f1hi = 0;
        {
            float slo = 0, sqlo = 0, shi = 0, sqhi = 0;
            #pragma unroll
            for (int nt = 0; nt < 16; nt++) {
                float2 bb = b2v[nt * 4 + t];
                c[nt][0] += bb.x; c[nt][1] += bb.y; c[nt][2] += bb.x; c[nt][3] += bb.y;
                slo += c[nt][0] + c[nt][1]; sqlo += c[nt][0] * c[nt][0] + c[nt][1] * c[nt][1];
                shi += c[nt][2] + c[nt][3]; sqhi += c[nt][2] * c[nt][2] + c[nt][3] * c[nt][3];
            }
            #pragma unroll
            for (int o = 1; o <= 2; o <<= 1) {
                slo += __shfl_xor_sync(~0u, slo, o); sqlo += __shfl_xor_sync(~0u, sqlo, o);
                shi += __shfl_xor_sync(~0u, shi, o); sqhi += __shfl_xor_sync(~0u, sqhi, o);
            }
            float mlo = slo * (1.f / 128.f), mhi = shi * (1.f / 128.f);
            float rlo = rsqrtf(sqlo * (1.f / 128.f) - mlo * mlo + LN_EPS);
            float rhi = rsqrtf(sqhi * (1.f / 128.f) - mhi * mhi + LN_EPS);
            #pragma unroll
            for (int nt = 0; nt < 16; nt++) {
                float2 ww = w2v[nt * 4 + t], lb = l2v[nt * 4 + t];
                float h0 = lrelu((c[nt][0] - mlo) * rlo * ww.x + lb.x);
                float h1 = lrelu((c[nt][1] - mlo) * rlo * ww.y + lb.y);
                float h2 = lrelu((c[nt][2] - mhi) * rhi * ww.x + lb.x);
                float h3 = lrelu((c[nt][3] - mhi) * rhi * ww.y + lb.y);
                float2 woa = wov[nt * 8 + 2 * t], wob = wov[nt * 8 + 2 * t + 1];
                f0lo += h0 * woa.x + h1 * wob.x;  f1lo += h0 * woa.y + h1 * wob.y;
                f0hi += h2 * woa.x + h3 * wob.x;  f1hi += h2 * woa.y + h3 * wob.y;
            }
            #pragma unroll
            for (int o = 1; o <= 2; o <<= 1) {
                f0lo += __shfl_xor_sync(~0u, f0lo, o); f1lo += __shfl_xor_sync(~0u, f1lo, o);
                f0hi += __shfl_xor_sync(~0u, f0hi, o); f1hi += __shfl_xor_sync(~0u, f1hi, o);
            }
        }

        // force-direction broadcasts (deferred to shrink live-register window)
        const int   v_lo = __shfl_sync(~0u, cval, g),  v_hi = __shfl_sync(~0u, cval, g + 8);
        const float d_lo = __shfl_sync(~0u, dist, g),  d_hi = __shfl_sync(~0u, dist, g + 8);
        const int   ii_lo = __shfl_sync(~0u, ci, g),   ii_hi = __shfl_sync(~0u, ci, g + 8);
        const int   jj_lo = __shfl_sync(~0u, cj, g),   jj_hi = __shfl_sync(~0u, cj, g + 8);
        const float dxl = __shfl_sync(~0u, dx, g), dyl = __shfl_sync(~0u, dy, g), dzl = __shfl_sync(~0u, dz, g);
        const float dxh = __shfl_sync(~0u, dx, g + 8), dyh = __shfl_sync(~0u, dy, g + 8), dzh = __shfl_sync(~0u, dz, g + 8);

        if (t == 0) {
            if (v_lo) {
                float rd = 1.f / d_lo;
                float ux = dxl * rd, uy = dyl * rd, uz = dzl * rd;
                float a0 = STEPU * (f0lo + bo0), a1 = STEPU * (f1lo + bo1);
                atomicAdd(&out[3 * ii_lo + 0],  a0 * ux);
                atomicAdd(&out[3 * ii_lo + 1],  a0 * uy);
                atomicAdd(&out[3 * ii_lo + 2],  a0 * uz);
                atomicAdd(&out[3 * jj_lo + 0], -a1 * ux);
                atomicAdd(&out[3 * jj_lo + 1], -a1 * uy);
                atomicAdd(&out[3 * jj_lo + 2], -a1 * uz);
            }
            if (v_hi) {
                float rd = 1.f / d_hi;
                float ux = dxh * rd, uy = dyh * rd, uz = dzh * rd;
                float a0 = STEPU * (f0hi + bo0), a1 = STEPU * (f1hi + bo1);
                atomicAdd(&out[3 * ii_hi + 0],  a0 * ux);
                atomicAdd(&out[3 * ii_hi + 1],  a0 * uy);
                atomicAdd(&out[3 * ii_hi + 2],  a0 * uz);
                atomicAdd(&out[3 * jj_hi + 0], -a1 * ux);
                atomicAdd(&out[3 * jj_hi + 1], -a1 * uy);
                atomicAdd(&out[3 * jj_hi + 2], -a1 * uz);
            }
        }
    }
}

// ---------------- launch ----------------
extern "C" void kernel_launch(void* const* d_in, const int* in_sizes, int n_in,
                              void* d_out, int out_size) {
    const float* x    = (const float*)d_in[0];
    const float* pos  = (const float*)d_in[1];
    const float* ne   = (const float*)d_in[2];
    const int*   bidx = (const int*)  d_in[3];
    const int*   btyp = (const int*)  d_in[4];
    const float* be   = (const float*)d_in[5];
    const float* W0   = (const float*)d_in[6];
    const float* b0   = (const float*)d_in[7];
    const float* W1   = (const float*)d_in[8];
    const float* b1   = (const float*)d_in[9];
    const float* l1w  = (const float*)d_in[10];
    const float* l1b  = (const float*)d_in[11];
    const float* W2   = (const float*)d_in[12];
    const float* b2   = (const float*)d_in[13];
    const float* l2w  = (const float*)d_in[14];
    const float* l2b  = (const float*)d_in[15];
    const float* Wo   = (const float*)d_in[16];
    const float* bo   = (const float*)d_in[17];
    float* out = (float*)d_out;

    cudaFuncSetAttribute(pq_kernel,   cudaFuncAttributeMaxDynamicSharedMemorySize, PQ_SMEM);
    cudaFuncSetAttribute(edge_kernel, cudaFuncAttributeMaxDynamicSharedMemorySize, EG_SMEM);

    int sms = 148;
    cudaDeviceGetAttribute(&sms, cudaDevAttrMultiProcessorCount, 0);

    // order: edge_kernel is the 4th launch (profiler lands on #4)
    pack_all<<<72, 256>>>(W0, W1, W2);                          // 1
    bond_table_kernel<<<1, 512>>>(be, W0, b0);                  // 2
    pq_kernel<<<(NN + 127) / 128, 256, PQ_SMEM>>>(ne, pos, (float*)d_out);  // 3
    edge_kernel<<<sms, 640, EG_SMEM>>>(x, bidx, btyp,           // 4 <- profiled
                                       b1, l1w, l1b, b2, l2w, l2b,
                                       Wo, bo, out);
}